// round 15
// baseline (speedup 1.0000x reference)
#include <cuda_runtime.h>
#include <cuda_fp16.h>
#include <math.h>
#include <stdint.h>

#define NPTS   400000
#define K27    27
#define TM     256
#define NT     1563      // ceil(400000/256)

// ---------------- global scratch (static; no allocation allowed) ----------------
// permuted activation layout: row = KCH*4 uint2; slot(tg,ch) = tg*KCH + ch,
// uint2 = ( halves(k0,k0+1), halves(k0+8,k0+9) ), k0 = ch*16 + tg*2
__device__ uint2 g_f16q[(size_t)NPTS * 16];   // features, KCH=4 (128 B/row)
__device__ uint2 g_hq  [(size_t)NPTS * 12];   // layer-1 acts,  KCH=3 ( 96 B/row)
__device__ uint2 g_W1f[27 * 5 * 4 * 32];      // W1 fragments [k][nb][ch][lane]
__device__ uint2 g_W2f[27 * 5 * 3 * 32];      // W2 fragments

#define MMA4(Dv, A0, A1, A2, A3, W) \
    asm volatile("mma.sync.aligned.m16n8k16.row.col.f32.f16.f16.f32 " \
        "{%0,%1,%2,%3}, {%4,%5,%6,%7}, {%8,%9}, {%0,%1,%2,%3};" \
        : "+f"((Dv)[0]), "+f"((Dv)[1]), "+f"((Dv)[2]), "+f"((Dv)[3]) \
        : "r"(A0), "r"(A1), "r"(A2), "r"(A3), "r"((W).x), "r"((W).y))

// ---------------- fused sparse-conv layer: M=32/warp, chunk-pipelined ----------
// KCH: k16 chunks (4 or 3)
template<int KCH, bool DO_GELU>
__global__ void __launch_bounds__(256, 2) conv_reg(
    const uint2* __restrict__ in, const int* __restrict__ nbr,
    const uint2* __restrict__ Wf, void* __restrict__ outp)
{
    constexpr int RS = KCH * 4;      // row stride in uint2
    __shared__ int sNbr[K27 * TM];

    const int tid  = threadIdx.x;
    const int lane = tid & 31;
    const int warp = tid >> 5;
    const int base = blockIdx.x * TM;

    #pragma unroll
    for (int e = tid; e < K27 * TM; e += 256) {
        const int r = base + (e & (TM - 1));
        sNbr[e] = (r < NPTS) ? nbr[(size_t)(e >> 8) * NPTS + r] : NPTS;
    }
    __syncthreads();

    const int gid  = lane >> 2;
    const int tg   = lane & 3;
    const int row0 = warp * 32 + gid;

    float D0[5][4], D1[5][4];
    #pragma unroll
    for (int nb = 0; nb < 5; nb++)
        #pragma unroll
        for (int j = 0; j < 4; j++) { D0[nb][j] = 0.0f; D1[nb][j] = 0.0f; }

    // predicated permuted-row chunk load
    auto ldrow = [&](int s, int ch) -> uint2 {
        uint2 z = make_uint2(0u, 0u);
        return (s != NPTS) ? in[(size_t)s * RS + tg * KCH + ch] : z;
    };

    // prologue: k=0 indices + chunk 0
    int a0 = sNbr[row0], a1 = sNbr[row0 + 8], a2 = sNbr[row0 + 16], a3 = sNbr[row0 + 24];
    uint2 c0 = ldrow(a0, 0), c1 = ldrow(a1, 0), c2 = ldrow(a2, 0), c3 = ldrow(a3, 0);

    #pragma unroll 1
    for (int k = 0; k < K27; k++) {
        const int kn = (k < K27 - 1) ? k + 1 : k;   // tail reloads k=26 (unused)
        const int b0 = sNbr[kn * TM + row0];
        const int b1 = sNbr[kn * TM + row0 + 8];
        const int b2 = sNbr[kn * TM + row0 + 16];
        const int b3 = sNbr[kn * TM + row0 + 24];
        const uint2* wp = Wf + (size_t)k * 5 * KCH * 32 + lane;

        #pragma unroll
        for (int ch = 0; ch < KCH; ch++) {
            uint2 n0, n1, n2, n3;
            if (ch + 1 < KCH) {
                n0 = ldrow(a0, ch + 1); n1 = ldrow(a1, ch + 1);
                n2 = ldrow(a2, ch + 1); n3 = ldrow(a3, ch + 1);
            } else {
                n0 = ldrow(b0, 0); n1 = ldrow(b1, 0);
                n2 = ldrow(b2, 0); n3 = ldrow(b3, 0);
            }
            #pragma unroll
            for (int nb = 0; nb < 5; nb++) {
                const uint2 w = wp[(nb * KCH + ch) * 32];
                MMA4(D0[nb], c0.x, c1.x, c0.y, c1.y, w);
                MMA4(D1[nb], c2.x, c3.x, c2.y, c3.y, w);
            }
            c0 = n0; c1 = n1; c2 = n2; c3 = n3;
        }
        a0 = b0; a1 = b1; a2 = b2; a3 = b3;
    }

    // ---- epilogue ----
    if (DO_GELU) {
        // emit layer-2 permuted layout (KCH=3, 24 uint32 per row) directly
        uint32_t* hp = (uint32_t*)outp;
        #pragma unroll
        for (int blk = 0; blk < 2; blk++) {
            float (*D)[4] = blk ? D1 : D0;
            const int ra = base + row0 + blk * 16, rb = ra + 8;
            #pragma unroll
            for (int nb = 0; nb < 5; nb++) {
                const int c    = nb * 8 + tg * 2;
                const int ch2  = c >> 4;
                const int pos  = c & 15;
                const int hi   = (pos >> 3) & 1;
                const int tg2  = (pos & 7) >> 1;
                const int slot = (tg2 * 3 + ch2) * 2 + hi;
                float x0 = D[nb][0]; x0 *= normcdff(x0);
                float x1 = D[nb][1]; x1 *= normcdff(x1);
                float x2 = D[nb][2]; x2 *= normcdff(x2);
                float x3 = D[nb][3]; x3 *= normcdff(x3);
                __half2 hA = __floats2half2_rn(x0, x1);
                __half2 hB = __floats2half2_rn(x2, x3);
                if (ra < NPTS) hp[(size_t)ra * 24 + slot] = *(uint32_t*)&hA;
                if (rb < NPTS) hp[(size_t)rb * 24 + slot] = *(uint32_t*)&hB;
            }
            const int zs = (tg * 3 + 2) * 2 + 1;   // pairs (40,42,44,46) -> zero
            if (ra < NPTS) hp[(size_t)ra * 24 + zs] = 0u;
            if (rb < NPTS) hp[(size_t)rb * 24 + zs] = 0u;
        }
    } else {
        float* op = (float*)outp;
        #pragma unroll
        for (int blk = 0; blk < 2; blk++) {
            float (*D)[4] = blk ? D1 : D0;
            const int ra = base + row0 + blk * 16, rb = ra + 8;
            #pragma unroll
            for (int nb = 0; nb < 5; nb++) {
                const int col = nb * 8 + tg * 2;
                if (col < 38) {
                    if (ra < NPTS)
                        *(float2*)(op + (size_t)ra * 38 + col) = make_float2(D[nb][0], D[nb][1]);
                    if (rb < NPTS)
                        *(float2*)(op + (size_t)rb * 38 + col) = make_float2(D[nb][2], D[nb][3]);
                }
            }
        }
    }
}

// ---------------- one-time conversions ----------------
// features -> permuted fp16 (KCH=4): one thread per uint2 slot
__global__ void cvt_feat(const float* __restrict__ f) {
    size_t i = (size_t)blockIdx.x * blockDim.x + threadIdx.x;
    if (i < (size_t)NPTS * 16) {
        const size_t r = i >> 4;
        const int s  = (int)(i & 15);
        const int tg = s >> 2, ch = s & 3;
        const int k0 = ch * 16 + tg * 2;
        const float2 lo = *(const float2*)(f + r * 64 + k0);
        const float2 hi = *(const float2*)(f + r * 64 + k0 + 8);
        __half2 hlo = __floats2half2_rn(lo.x, lo.y);
        __half2 hhi = __floats2half2_rn(hi.x, hi.y);
        g_f16q[i] = make_uint2(*(uint32_t*)&hlo, *(uint32_t*)&hhi);
    }
}

// fragment packing: per (k, nb, ch, lane): n = nb*8 + lane/4, kk0 = ch*16 + (lane%4)*2
template<int KW, int KCH>
__device__ __forceinline__ void pack_one(const float* W, uint2* Wf, int i) {
    int lane = i & 31, ch = (i >> 5) % KCH, nb = (i / (32 * KCH)) % 5, k = i / (32 * KCH * 5);
    int n = nb * 8 + (lane >> 2);
    int kk0 = ch * 16 + (lane & 3) * 2;
    const float* Wk = W + (size_t)k * KW * 38;
    auto val = [&](int kk) -> float {
        return (n < 38 && kk < KW) ? Wk[kk * 38 + n] : 0.0f;
    };
    __half2 b0 = __floats2half2_rn(val(kk0),     val(kk0 + 1));
    __half2 b1 = __floats2half2_rn(val(kk0 + 8), val(kk0 + 9));
    Wf[i] = make_uint2(*(uint32_t*)&b0, *(uint32_t*)&b1);
}
__global__ void cvt_w(const float* __restrict__ W1, const float* __restrict__ W2) {
    int i = blockIdx.x * blockDim.x + threadIdx.x;
    if (i < 27 * 5 * 4 * 32) pack_one<64, 4>(W1, g_W1f, i);
    if (i < 27 * 5 * 3 * 32) pack_one<38, 3>(W2, g_W2f, i);
}

extern "C" void kernel_launch(void* const* d_in, const int* in_sizes, int n_in,
                              void* d_out, int out_size)
{
    const float* feat = nullptr;
    const int*   nbr  = nullptr;
    const float* W1   = nullptr;
    const float* W2   = nullptr;
    for (int i = 0; i < n_in; i++) {
        long s = in_sizes[i];
        if      (s == (long)NPTS * 64)      feat = (const float*)d_in[i];
        else if (s == (long)K27 * NPTS)     nbr  = (const int*)d_in[i];
        else if (s == (long)27 * 64 * 38)   W1   = (const float*)d_in[i];
        else if (s == (long)27 * 38 * 38)   W2   = (const float*)d_in[i];
    }
    float* out = (float*)d_out;
    uint2 *fq, *hq, *w1p, *w2p;
    cudaGetSymbolAddress((void**)&fq,  g_f16q);
    cudaGetSymbolAddress((void**)&hq,  g_hq);
    cudaGetSymbolAddress((void**)&w1p, g_W1f);
    cudaGetSymbolAddress((void**)&w2p, g_W2f);

    cvt_feat<<<(int)(((size_t)NPTS * 16 + 255) / 256), 256>>>(feat);
    cvt_w<<<(27 * 5 * 4 * 32 + 255) / 256, 256>>>(W1, W2);
    conv_reg<4, true ><<<NT, 256>>>(fq, nbr, w1p, hq);
    conv_reg<3, false><<<NT, 256>>>(hq, nbr, w2p, out);
}

// round 16
// speedup vs baseline: 1.2102x; 1.2102x over previous
#include <cuda_runtime.h>
#include <cuda_fp16.h>
#include <math.h>
#include <stdint.h>

#define NPTS   400000
#define K27    27
#define TM     256
#define NT     1563      // ceil(400000/256)

// ---------------- global scratch (static; no allocation allowed) ----------------
__device__ __half g_f16[(size_t)NPTS * 64];     // features fp16 (natural layout)
__device__ __half g_h  [(size_t)NPTS * 48];     // layer-1 activations fp16, padded to 48
__device__ uint2  g_W1f[27 * 5 * 4 * 32];       // fragment-packed W1: [k][nb][ch][lane]
__device__ uint2  g_W2f[27 * 5 * 3 * 32];       // fragment-packed W2

// ---------------- fused sparse-conv layer, 32 rows/warp, register accumulation --
// CIN: fp16 row width (64 or 48), KCH: k16 chunks (4 or 3)
template<int CIN, int KCH, bool DO_GELU>
__global__ void __launch_bounds__(256, 3) conv_reg(
    const __half* __restrict__ in, const int* __restrict__ nbr,
    const uint2* __restrict__ Wf, void* __restrict__ outp)
{
    __shared__ int sNbr[K27 * TM];

    const int tid  = threadIdx.x;
    const int lane = tid & 31;
    const int warp = tid >> 5;
    const int base = blockIdx.x * TM;

    #pragma unroll
    for (int e = tid; e < K27 * TM; e += 256) {
        const int r = base + (e & (TM - 1));
        sNbr[e] = (r < NPTS) ? nbr[(size_t)(e >> 8) * NPTS + r] : NPTS;
    }
    __syncthreads();

    const int gid  = lane >> 2;      // fragment row group 0..7
    const int tg   = lane & 3;       // fragment col group 0..3
    const int row0 = warp * 32 + gid;

    float D0[5][4], D1[5][4];
    #pragma unroll
    for (int nb = 0; nb < 5; nb++)
        #pragma unroll
        for (int j = 0; j < 4; j++) { D0[nb][j] = 0.0f; D1[nb][j] = 0.0f; }

    #pragma unroll 1
    for (int k = 0; k < K27; k++) {
        const int s0 = sNbr[k * TM + row0];
        const int s1 = sNbr[k * TM + row0 + 8];
        const int s2 = sNbr[k * TM + row0 + 16];
        const int s3 = sNbr[k * TM + row0 + 24];
        const bool v0 = (s0 != NPTS), v1 = (s1 != NPTS);
        const bool v2 = (s2 != NPTS), v3 = (s3 != NPTS);
        if (!__ballot_sync(0xFFFFFFFFu, v0 || v1 || v2 || v3)) continue;

        const __half* p0 = in + (size_t)s0 * CIN + tg * 2;
        const __half* p1 = in + (size_t)s1 * CIN + tg * 2;
        const __half* p2 = in + (size_t)s2 * CIN + tg * 2;
        const __half* p3 = in + (size_t)s3 * CIN + tg * 2;
        const uint2* wp = Wf + (size_t)k * 5 * KCH * 32 + lane;

        #pragma unroll
        for (int ch = 0; ch < KCH; ch++) {
            const int off = ch * 16;
            const uint32_t a0 = v0 ? *(const uint32_t*)(p0 + off)     : 0u;
            const uint32_t a1 = v1 ? *(const uint32_t*)(p1 + off)     : 0u;
            const uint32_t a2 = v0 ? *(const uint32_t*)(p0 + off + 8) : 0u;
            const uint32_t a3 = v1 ? *(const uint32_t*)(p1 + off + 8) : 0u;
            const uint32_t b0 = v2 ? *(const uint32_t*)(p2 + off)     : 0u;
            const uint32_t b1 = v3 ? *(const uint32_t*)(p3 + off)     : 0u;
            const uint32_t b2 = v2 ? *(const uint32_t*)(p2 + off + 8) : 0u;
            const uint32_t b3 = v3 ? *(const uint32_t*)(p3 + off + 8) : 0u;

            #pragma unroll
            for (int nb = 0; nb < 5; nb++) {
                const uint2 w = wp[(nb * KCH + ch) * 32];   // loaded once, used twice
                asm volatile(
                    "mma.sync.aligned.m16n8k16.row.col.f32.f16.f16.f32 "
                    "{%0,%1,%2,%3}, {%4,%5,%6,%7}, {%8,%9}, {%0,%1,%2,%3};"
                    : "+f"(D0[nb][0]), "+f"(D0[nb][1]), "+f"(D0[nb][2]), "+f"(D0[nb][3])
                    : "r"(a0), "r"(a1), "r"(a2), "r"(a3), "r"(w.x), "r"(w.y));
                asm volatile(
                    "mma.sync.aligned.m16n8k16.row.col.f32.f16.f16.f32 "
                    "{%0,%1,%2,%3}, {%4,%5,%6,%7}, {%8,%9}, {%0,%1,%2,%3};"
                    : "+f"(D1[nb][0]), "+f"(D1[nb][1]), "+f"(D1[nb][2]), "+f"(D1[nb][3])
                    : "r"(b0), "r"(b1), "r"(b2), "r"(b3), "r"(w.x), "r"(w.y));
            }
        }
    }

    // ---- epilogue ----
    const int r0 = base + row0;          // D0 rows: r0, r0+8 ; D1 rows: r0+16, r0+24
    if (DO_GELU) {
        uint32_t* hp = (uint32_t*)g_h;   // row stride 24 uint32 (48 halves)
        #pragma unroll
        for (int blk = 0; blk < 2; blk++) {
            float (*D)[4] = blk ? D1 : D0;
            const int ra = r0 + blk * 16, rb = ra + 8;
            #pragma unroll
            for (int nb = 0; nb < 5; nb++) {
                const int cw = (nb * 8 + tg * 2) >> 1;
                float x0 = D[nb][0]; x0 *= normcdff(x0);
                float x1 = D[nb][1]; x1 *= normcdff(x1);
                float x2 = D[nb][2]; x2 *= normcdff(x2);
                float x3 = D[nb][3]; x3 *= normcdff(x3);
                __half2 hA = __floats2half2_rn(x0, x1);
                __half2 hB = __floats2half2_rn(x2, x3);
                if (ra < NPTS) hp[(size_t)ra * 24 + cw] = *(uint32_t*)&hA;
                if (rb < NPTS) hp[(size_t)rb * 24 + cw] = *(uint32_t*)&hB;
            }
            if (ra < NPTS) hp[(size_t)ra * 24 + 20 + tg] = 0u;   // pad cols 40..47
            if (rb < NPTS) hp[(size_t)rb * 24 + 20 + tg] = 0u;
        }
    } else {
        float* op = (float*)outp;
        #pragma unroll
        for (int blk = 0; blk < 2; blk++) {
            float (*D)[4] = blk ? D1 : D0;
            const int ra = r0 + blk * 16, rb = ra + 8;
            #pragma unroll
            for (int nb = 0; nb < 5; nb++) {
                const int col = nb * 8 + tg * 2;
                if (col < 38) {
                    if (ra < NPTS)
                        *(float2*)(op + (size_t)ra * 38 + col) = make_float2(D[nb][0], D[nb][1]);
                    if (rb < NPTS)
                        *(float2*)(op + (size_t)rb * 38 + col) = make_float2(D[nb][2], D[nb][3]);
                }
            }
        }
    }
}

// ---------------- one-time conversions ----------------
__global__ void cvt_feat(const float* __restrict__ f) {
    size_t i = (size_t)blockIdx.x * blockDim.x + threadIdx.x;
    const size_t n4 = (size_t)NPTS * 64 / 4;
    if (i < n4) {
        float4 v = ((const float4*)f)[i];
        __half2* o = (__half2*)g_f16;
        o[i * 2 + 0] = __floats2half2_rn(v.x, v.y);
        o[i * 2 + 1] = __floats2half2_rn(v.z, v.w);
    }
}

// fragment packing: per (k, nb, ch, lane): n = nb*8 + lane/4, kk0 = ch*16 + (lane%4)*2
template<int KW, int KCH>
__device__ __forceinline__ void pack_one(const float* W, uint2* Wf, int i) {
    int lane = i & 31, ch = (i >> 5) % KCH, nb = (i / (32 * KCH)) % 5, k = i / (32 * KCH * 5);
    int n = nb * 8 + (lane >> 2);
    int kk0 = ch * 16 + (lane & 3) * 2;
    const float* Wk = W + (size_t)k * KW * 38;
    auto val = [&](int kk) -> float {
        return (n < 38 && kk < KW) ? Wk[kk * 38 + n] : 0.0f;
    };
    __half2 b0 = __floats2half2_rn(val(kk0),     val(kk0 + 1));
    __half2 b1 = __floats2half2_rn(val(kk0 + 8), val(kk0 + 9));
    Wf[i] = make_uint2(*(uint32_t*)&b0, *(uint32_t*)&b1);
}
__global__ void cvt_w(const float* __restrict__ W1, const float* __restrict__ W2) {
    int i = blockIdx.x * blockDim.x + threadIdx.x;
    if (i < 27 * 5 * 4 * 32) pack_one<64, 4>(W1, g_W1f, i);
    if (i < 27 * 5 * 3 * 32) pack_one<38, 3>(W2, g_W2f, i);
}

extern "C" void kernel_launch(void* const* d_in, const int* in_sizes, int n_in,
                              void* d_out, int out_size)
{
    const float* feat = nullptr;
    const int*   nbr  = nullptr;
    const float* W1   = nullptr;
    const float* W2   = nullptr;
    for (int i = 0; i < n_in; i++) {
        long s = in_sizes[i];
        if      (s == (long)NPTS * 64)      feat = (const float*)d_in[i];
        else if (s == (long)K27 * NPTS)     nbr  = (const int*)d_in[i];
        else if (s == (long)27 * 64 * 38)   W1   = (const float*)d_in[i];
        else if (s == (long)27 * 38 * 38)   W2   = (const float*)d_in[i];
    }
    float* out = (float*)d_out;
    __half *f16p, *hp;
    uint2 *w1p, *w2p;
    cudaGetSymbolAddress((void**)&f16p, g_f16);
    cudaGetSymbolAddress((void**)&hp,   g_h);
    cudaGetSymbolAddress((void**)&w1p,  g_W1f);
    cudaGetSymbolAddress((void**)&w2p,  g_W2f);

    cvt_feat<<<(NPTS * 64 / 4 + 255) / 256, 256>>>(feat);
    cvt_w<<<(27 * 5 * 4 * 32 + 255) / 256, 256>>>(W1, W2);
    conv_reg<64, 4, true ><<<NT, 256>>>(f16p, nbr, w1p, hp);
    conv_reg<48, 3, false><<<NT, 256>>>(hp,   nbr, w2p, out);
}